// round 1
// baseline (speedup 1.0000x reference)
#include <cuda_runtime.h>
#include <cuda_bf16.h>
#include <math.h>
#include <stdint.h>

// Problem constants
#define B_ROWS 16384
#define D_DIM  2048
#define H_DIM  512

// ---------------------------------------------------------------------------
// Scratch (no allocations allowed; __device__ globals are the sanctioned path)
// ---------------------------------------------------------------------------
__device__ float g_h[(size_t)B_ROWS * H_DIM];   // relu(x@W1) : 32 MB
__device__ float g_rowsum[B_ROWS];              // per-row sum |sparse_x|

// ---------------------------------------------------------------------------
// Kernel 1: H = relu(X @ W1 + b1)   fp32 SIMT GEMM, 128x128x8 tiles, 8x8/thread
//   X  [16384, 2048] row-major
//   W1 [2048, 512]   row-major ([in, out])
//   H  [16384, 512]
// ---------------------------------------------------------------------------
#define BM 128
#define BN 128
#define BK 8

__global__ void __launch_bounds__(256, 2)
gemm_relu_kernel(const float* __restrict__ X,
                 const float* __restrict__ W1,
                 const float* __restrict__ b1,
                 float* __restrict__ H)
{
    __shared__ float As[BK][BM];
    __shared__ float Bs[BK][BN];

    const int tid = threadIdx.x;
    const int bm = blockIdx.y * BM;
    const int bn = blockIdx.x * BN;

    // A-tile load mapping: 128 rows x 8 k -> 1024 floats, one float4/thread
    const int a_row = tid >> 1;          // 0..127
    const int a_col = (tid & 1) * 4;     // 0 or 4
    // B-tile load mapping: 8 k-rows x 128 cols
    const int b_row = tid >> 5;          // 0..7
    const int b_col = (tid & 31) * 4;    // 0..124

    const int tx = tid & 15;             // 0..15 (8-col group)
    const int ty = tid >> 4;             // 0..15 (8-row group)

    float acc[8][8];
#pragma unroll
    for (int i = 0; i < 8; i++)
#pragma unroll
        for (int j = 0; j < 8; j++) acc[i][j] = 0.0f;

    const float* Ap = X + (size_t)(bm + a_row) * D_DIM + a_col;
    const float* Bp = W1 + (size_t)b_row * H_DIM + bn + b_col;

    for (int k0 = 0; k0 < D_DIM; k0 += BK) {
        float4 av = *(const float4*)(Ap + k0);
        float4 bv = *(const float4*)(Bp + (size_t)k0 * H_DIM);
        As[a_col + 0][a_row] = av.x;
        As[a_col + 1][a_row] = av.y;
        As[a_col + 2][a_row] = av.z;
        As[a_col + 3][a_row] = av.w;
        *(float4*)&Bs[b_row][b_col] = bv;
        __syncthreads();

#pragma unroll
        for (int kk = 0; kk < BK; kk++) {
            float ar[8], br[8];
#pragma unroll
            for (int i = 0; i < 8; i++) ar[i] = As[kk][ty * 8 + i];
#pragma unroll
            for (int j = 0; j < 8; j++) br[j] = Bs[kk][tx * 8 + j];
#pragma unroll
            for (int i = 0; i < 8; i++)
#pragma unroll
                for (int j = 0; j < 8; j++)
                    acc[i][j] = fmaf(ar[i], br[j], acc[i][j]);
        }
        __syncthreads();
    }

    // epilogue: + b1, relu, store
    float bb[8];
#pragma unroll
    for (int j = 0; j < 8; j++) bb[j] = b1[bn + tx * 8 + j];

#pragma unroll
    for (int i = 0; i < 8; i++) {
        const int m = bm + ty * 8 + i;
        float4 v0, v1;
        v0.x = fmaxf(acc[i][0] + bb[0], 0.0f);
        v0.y = fmaxf(acc[i][1] + bb[1], 0.0f);
        v0.z = fmaxf(acc[i][2] + bb[2], 0.0f);
        v0.w = fmaxf(acc[i][3] + bb[3], 0.0f);
        v1.x = fmaxf(acc[i][4] + bb[4], 0.0f);
        v1.y = fmaxf(acc[i][5] + bb[5], 0.0f);
        v1.z = fmaxf(acc[i][6] + bb[6], 0.0f);
        v1.w = fmaxf(acc[i][7] + bb[7], 0.0f);
        float* hp = H + (size_t)m * H_DIM + bn + tx * 8;
        *(float4*)(hp + 0) = v0;
        *(float4*)(hp + 4) = v1;
    }
}

// ---------------------------------------------------------------------------
// Kernel 2: per-row (one CTA per row):
//   z = h@W2 + b2 ; sig ; sparsity ; k ; exact k-th smallest |x| by radix
//   select on bit pattern; write mask / sparse_x / actual_sparsity / rowsum
// ---------------------------------------------------------------------------
__global__ void __launch_bounds__(256)
select_kernel(const float* __restrict__ X,
              const float* __restrict__ W2,
              const float* __restrict__ b2,
              const float* __restrict__ H,
              float* __restrict__ sparse_out,
              float* __restrict__ mask_out,
              float* __restrict__ sparsity_out,
              float* __restrict__ actsp_out,
              float* __restrict__ rowsum_out)
{
    __shared__ unsigned sx[D_DIM];     // original x bits of the row
    __shared__ unsigned hist[256];
    __shared__ float red[256];
    __shared__ unsigned s_prefix;
    __shared__ int s_kk;

    const int row = blockIdx.x;
    const int tid = threadIdx.x;
    const float* xr = X + (size_t)row * D_DIM;

    // load row bits into smem
    for (int i = tid; i < D_DIM; i += 256)
        sx[i] = __float_as_uint(xr[i]);

    // z = dot(h_row, W2)  (deterministic tree reduce)
    {
        const float* hr = H + (size_t)row * H_DIM;
        float p = 0.0f;
        for (int j = tid; j < H_DIM; j += 256)
            p = fmaf(hr[j], W2[j], p);
        red[tid] = p;
        __syncthreads();
        for (int s = 128; s > 0; s >>= 1) {
            if (tid < s) red[tid] += red[tid + s];
            __syncthreads();
        }
    }
    const float z = red[0] + b2[0];
    const float sig = 1.0f / (1.0f + expf(-z));
    const float sp = 0.05f + 0.25f * sig;                       // MIN_S + (MAX_S-MIN_S)*sig
    const int k = max(1, (int)rintf((float)D_DIM * (1.0f - sp))); // half-even like jnp.round
    if (tid == 0) sparsity_out[row] = sp;
    __syncthreads();  // done with red before reuse; sx fully written

    // MSB-first 8-bit radix select: k-th smallest abs bit pattern
    unsigned prefix = 0;
    int kk = k;
#pragma unroll
    for (int shift = 24; shift >= 0; shift -= 8) {
        hist[tid] = 0;
        __syncthreads();
        const unsigned himask = (shift == 24) ? 0u : (0xffffffffu << (shift + 8));
        for (int i = tid; i < D_DIM; i += 256) {
            const unsigned a = sx[i] & 0x7fffffffu;
            const bool pred = (a & himask) == prefix;
            const unsigned bin = (a >> shift) & 255u;
            // warp-aggregated histogram (abs exponents are heavily concentrated)
            const unsigned key = pred ? bin : 0xffffffffu;
            const unsigned grp = __match_any_sync(0xffffffffu, key);
            if (pred) {
                const int leader = __ffs(grp) - 1;
                if ((tid & 31) == leader)
                    atomicAdd(&hist[bin], __popc(grp));
            }
        }
        __syncthreads();
        if (tid == 0) {
            int c = kk;
            unsigned d = 0;
            for (d = 0; d < 256; d++) {
                const int hv = (int)hist[d];
                if (c <= hv) break;
                c -= hv;
            }
            s_prefix = prefix | (d << shift);
            s_kk = c;
        }
        __syncthreads();
        prefix = s_prefix;
        kk = s_kk;
        __syncthreads();
    }
    const unsigned thresh = prefix;  // exact bit pattern of k-th smallest |x|

    // write mask / sparse_x, accumulate count & |sum|
    int cnt = 0;
    float asum = 0.0f;
    for (int i = tid; i < D_DIM; i += 256) {
        const unsigned u = sx[i];
        const unsigned a = u & 0x7fffffffu;
        const bool m = a > thresh;   // integer compare == float compare for abs values
        const float xv = __uint_as_float(u);
        const size_t idx = (size_t)row * D_DIM + i;
        mask_out[idx] = m ? 1.0f : 0.0f;
        sparse_out[idx] = m ? xv : 0.0f;
        if (m) { cnt++; asum += fabsf(xv); }
    }

    red[tid] = asum;
    __syncthreads();
    for (int s = 128; s > 0; s >>= 1) {
        if (tid < s) red[tid] += red[tid + s];
        __syncthreads();
    }
    const float tot_sum = red[0];
    __syncthreads();
    red[tid] = (float)cnt;
    __syncthreads();
    for (int s = 128; s > 0; s >>= 1) {
        if (tid < s) red[tid] += red[tid + s];
        __syncthreads();
    }
    if (tid == 0) {
        actsp_out[row] = red[0] / (float)D_DIM;
        rowsum_out[row] = tot_sum;
    }
}

// ---------------------------------------------------------------------------
// Kernel 3: l1_reg = mean(rowsum)
// ---------------------------------------------------------------------------
__global__ void __launch_bounds__(256)
l1_reduce_kernel(const float* __restrict__ rowsum, float* __restrict__ out)
{
    __shared__ float red[256];
    const int tid = threadIdx.x;
    float p = 0.0f;
    for (int i = tid; i < B_ROWS; i += 256) p += rowsum[i];
    red[tid] = p;
    __syncthreads();
    for (int s = 128; s > 0; s >>= 1) {
        if (tid < s) red[tid] += red[tid + s];
        __syncthreads();
    }
    if (tid == 0) out[0] = red[0] / (float)B_ROWS;
}

// ---------------------------------------------------------------------------
// Launch: outputs concatenated in reference return order (all fp32):
//   sparse_x [B,D] | mask [B,D] | sparsity [B,1] | actual_sparsity [B] | l1 [1]
// ---------------------------------------------------------------------------
extern "C" void kernel_launch(void* const* d_in, const int* in_sizes, int n_in,
                              void* d_out, int out_size)
{
    const float* X  = (const float*)d_in[0];
    const float* W1 = (const float*)d_in[1];
    const float* b1 = (const float*)d_in[2];
    const float* W2 = (const float*)d_in[3];
    const float* b2 = (const float*)d_in[4];

    float* out = (float*)d_out;
    float* sparse_x = out;
    float* mask     = out + (size_t)B_ROWS * D_DIM;
    float* spars    = out + (size_t)2 * B_ROWS * D_DIM;
    float* actsp    = spars + B_ROWS;
    float* l1       = actsp + B_ROWS;

    float* hbuf;
    float* rowsum;
    cudaGetSymbolAddress((void**)&hbuf, g_h);
    cudaGetSymbolAddress((void**)&rowsum, g_rowsum);

    dim3 ggrid(H_DIM / BN, B_ROWS / BM);  // (4, 128)
    gemm_relu_kernel<<<ggrid, 256>>>(X, W1, b1, hbuf);

    select_kernel<<<B_ROWS, 256>>>(X, W2, b2, hbuf,
                                   sparse_x, mask, spars, actsp, rowsum);

    l1_reduce_kernel<<<1, 256>>>(rowsum, l1);
}

// round 4
// speedup vs baseline: 1.4910x; 1.4910x over previous
#include <cuda_runtime.h>
#include <cuda_bf16.h>
#include <math.h>
#include <stdint.h>

#define B_ROWS 16384
#define D_DIM  2048
#define H_DIM  512

// ---------------------------------------------------------------------------
// Scratch (device globals; no allocations allowed)
// ---------------------------------------------------------------------------
__device__ __nv_bfloat16 g_w1s[3][H_DIM][D_DIM];  // W1^T 3-way bf16 split (6MB)
__device__ float g_zpart[4][B_ROWS];              // per-N-block partial z
__device__ float g_rowsum[B_ROWS];

__device__ __forceinline__ uint32_t pk(__nv_bfloat16 a, __nv_bfloat16 b) {
    return (uint32_t)__bfloat16_as_ushort(a) | ((uint32_t)__bfloat16_as_ushort(b) << 16);
}

__device__ __forceinline__ void mma16816(float* c, const uint32_t* a, const uint32_t* b) {
    asm volatile("mma.sync.aligned.m16n8k16.row.col.f32.bf16.bf16.f32 "
                 "{%0,%1,%2,%3}, {%4,%5,%6,%7}, {%8,%9}, {%0,%1,%2,%3};"
                 : "+f"(c[0]), "+f"(c[1]), "+f"(c[2]), "+f"(c[3])
                 : "r"(a[0]), "r"(a[1]), "r"(a[2]), "r"(a[3]),
                   "r"(b[0]), "r"(b[1]));
}

// ---------------------------------------------------------------------------
// Kernel 0: split + transpose W1 [2048,512] fp32 -> g_w1s[3][512][2048] bf16
// ---------------------------------------------------------------------------
__global__ void __launch_bounds__(1024)
split_w1_kernel(const float* __restrict__ W1)
{
    __shared__ float tile[32][33];
    const int k0 = blockIdx.x * 32, n0 = blockIdx.y * 32;
    tile[threadIdx.y][threadIdx.x] =
        W1[(size_t)(k0 + threadIdx.y) * H_DIM + n0 + threadIdx.x];
    __syncthreads();
    const float v = tile[threadIdx.x][threadIdx.y];   // = W1[k0+tx][n0+ty]
    const int n = n0 + threadIdx.y, k = k0 + threadIdx.x;
    __nv_bfloat16 h0 = __float2bfloat16_rn(v);
    float r1 = v - __bfloat162float(h0);
    __nv_bfloat16 h1 = __float2bfloat16_rn(r1);
    float r2 = r1 - __bfloat162float(h1);
    g_w1s[0][n][k] = h0;
    g_w1s[1][n][k] = h1;
    g_w1s[2][n][k] = __float2bfloat16_rn(r2);
}

// ---------------------------------------------------------------------------
// Kernel 1: fused z-partials via mma.sync bf16 3-way-split emulated-fp32 GEMM
//   CTA tile: 128(M) x 128(N), K chunks of 32. 8 warps (2x4), warp tile 64x32.
//   Epilogue: zpart[row] = sum_n relu(c[row][n]+b1[n]) * W2[n]  (per N-block)
//   SMEM (dynamic, 64512 B):
//     [0      .. 30720) As[3][128][40] bf16   (pad stride 40 halves)
//     [30720  .. 61440) Bs[3][128][40] bf16   ([n][k] layout = col-major B)
//     [61440  .. 61952) b1s[128] f32
//     [61952  .. 62464) w2s[128] f32
//     [62464  .. 64512) zred[4][128] f32
// ---------------------------------------------------------------------------
#define SMEM_BYTES 64512

__global__ void __launch_bounds__(256, 2)
gemm_z_kernel(const float* __restrict__ X,
              const float* __restrict__ b1,
              const float* __restrict__ W2)
{
    extern __shared__ char sm[];
    uint32_t* smw = (uint32_t*)sm;
    float* b1s  = (float*)(sm + 61440);
    float* w2s  = (float*)(sm + 61952);
    float* zred = (float*)(sm + 62464);

    const int tid  = threadIdx.x;
    const int nblk = blockIdx.x;            // 0..3
    const int bn   = nblk * 128;
    const int bm   = blockIdx.y * 128;
    const int warp = tid >> 5, lane = tid & 31;
    const int grp  = lane >> 2, four = lane & 3;
    const int wm   = (warp >> 2) * 64;      // 0 or 64
    const int wn   = (warp & 3) * 32;       // 0,32,64,96

    if (tid < 128) { b1s[tid] = b1[bn + tid]; w2s[tid] = W2[bn + tid]; }

    float acc[4][4][4];
#pragma unroll
    for (int mt = 0; mt < 4; mt++)
#pragma unroll
        for (int nt = 0; nt < 4; nt++)
#pragma unroll
            for (int j = 0; j < 4; j++) acc[mt][nt][j] = 0.0f;

    const float* Xp = X + (size_t)bm * D_DIM;

    for (int kc = 0; kc < 64; kc++) {
        __syncthreads();  // previous chunk's frag reads done before overwrite

        // ---- A: load 128x32 fp32, split into 3 bf16 tiles
#pragma unroll
        for (int i = 0; i < 4; i++) {
            const int f = i * 256 + tid;
            const int r = f >> 3, c4 = f & 7;
            const float4 v = *(const float4*)(Xp + (size_t)r * D_DIM + kc * 32 + c4 * 4);
            const float e[4] = {v.x, v.y, v.z, v.w};
            __nv_bfloat16 s0[4], s1[4], s2[4];
#pragma unroll
            for (int j = 0; j < 4; j++) {
                const float x = e[j];
                __nv_bfloat16 h0 = __float2bfloat16_rn(x);
                float r1 = x - __bfloat162float(h0);
                __nv_bfloat16 h1 = __float2bfloat16_rn(r1);
                float r2 = r1 - __bfloat162float(h1);
                s0[j] = h0; s1[j] = h1; s2[j] = __float2bfloat16_rn(r2);
            }
            const uint32_t off = (uint32_t)(r * 80 + c4 * 8);
            *(uint2*)(sm +     0 + off) = make_uint2(pk(s0[0], s0[1]), pk(s0[2], s0[3]));
            *(uint2*)(sm + 10240 + off) = make_uint2(pk(s1[0], s1[1]), pk(s1[2], s1[3]));
            *(uint2*)(sm + 20480 + off) = make_uint2(pk(s2[0], s2[1]), pk(s2[2], s2[3]));
        }

        // ---- B: 3 pre-split tiles [n][k] 128x32 bf16
#pragma unroll
        for (int s = 0; s < 3; s++)
#pragma unroll
            for (int j = 0; j < 2; j++) {
                const int f = j * 256 + tid;
                const int n = f >> 2, q = f & 3;
                const uint4 v = *(const uint4*)&g_w1s[s][bn + n][kc * 32 + q * 8];
                *(uint4*)(sm + 30720 + s * 10240 + n * 80 + q * 16) = v;
            }
        __syncthreads();

        // ---- MMA: 6 split terms, 2 k-steps of 16
#pragma unroll
        for (int ks = 0; ks < 2; ks++) {
            uint32_t bf[3][4][2];
#pragma unroll
            for (int s = 0; s < 3; s++)
#pragma unroll
                for (int nt = 0; nt < 4; nt++) {
                    const int bw = 7680 + s * 2560 + (wn + nt * 8 + grp) * 20 + ks * 8 + four;
                    bf[s][nt][0] = smw[bw];
                    bf[s][nt][1] = smw[bw + 4];
                }
#pragma unroll
            for (int mt = 0; mt < 4; mt++) {
                uint32_t af[3][4];
#pragma unroll
                for (int s = 0; s < 3; s++) {
                    const int aw = s * 2560 + (wm + mt * 16 + grp) * 20 + ks * 8 + four;
                    af[s][0] = smw[aw];
                    af[s][1] = smw[aw + 160];
                    af[s][2] = smw[aw + 4];
                    af[s][3] = smw[aw + 164];
                }
#pragma unroll
                for (int nt = 0; nt < 4; nt++) {
                    mma16816(acc[mt][nt], af[0], bf[0][nt]);
                    mma16816(acc[mt][nt], af[1], bf[0][nt]);
                    mma16816(acc[mt][nt], af[0], bf[1][nt]);
                    mma16816(acc[mt][nt], af[1], bf[1][nt]);
                    mma16816(acc[mt][nt], af[2], bf[0][nt]);
                    mma16816(acc[mt][nt], af[0], bf[2][nt]);
                }
            }
        }
    }

    // ---- epilogue: zpart[row] = sum_n relu(c+b1)*w2 over this CTA's 128 cols
    __syncthreads();
#pragma unroll
    for (int mt = 0; mt < 4; mt++) {
        float p0 = 0.0f, p1 = 0.0f;
#pragma unroll
        for (int nt = 0; nt < 4; nt++) {
            const int n0 = wn + nt * 8 + four * 2;
            p0 = fmaf(fmaxf(acc[mt][nt][0] + b1s[n0], 0.0f),     w2s[n0],     p0);
            p0 = fmaf(fmaxf(acc[mt][nt][1] + b1s[n0 + 1], 0.0f), w2s[n0 + 1], p0);
            p1 = fmaf(fmaxf(acc[mt][nt][2] + b1s[n0], 0.0f),     w2s[n0],     p1);
            p1 = fmaf(fmaxf(acc[mt][nt][3] + b1s[n0 + 1], 0.0f), w2s[n0 + 1], p1);
        }
        p0 += __shfl_xor_sync(0xffffffffu, p0, 1);
        p0 += __shfl_xor_sync(0xffffffffu, p0, 2);
        p1 += __shfl_xor_sync(0xffffffffu, p1, 1);
        p1 += __shfl_xor_sync(0xffffffffu, p1, 2);
        if (four == 0) {
            zred[(warp & 3) * 128 + wm + mt * 16 + grp]     = p0;
            zred[(warp & 3) * 128 + wm + mt * 16 + grp + 8] = p1;
        }
    }
    __syncthreads();
    if (tid < 128) {
        const float z = (zred[tid] + zred[128 + tid])
                      + (zred[256 + tid] + zred[384 + tid]);
        g_zpart[nblk][bm + tid] = z;
    }
}

// ---------------------------------------------------------------------------
// Kernel 2: per-row z -> sigmoid -> k; exact k-th |x| radix select; outputs
// ---------------------------------------------------------------------------
__global__ void __launch_bounds__(256)
select_kernel(const float* __restrict__ X,
              const float* __restrict__ b2,
              float* __restrict__ sparse_out,
              float* __restrict__ mask_out,
              float* __restrict__ sparsity_out,
              float* __restrict__ actsp_out)
{
    __shared__ uint32_t sx[D_DIM];
    __shared__ uint32_t hist[256];
    __shared__ float    fwarp[8];
    __shared__ uint32_t uwarp[8];
    __shared__ uint32_t s_prefix;
    __shared__ int      s_kk;
    __shared__ int      s_k;

    const int row = blockIdx.x, tid = threadIdx.x;
    const int lane = tid & 31, wid = tid >> 5;
    const uint4* xr = (const uint4*)(X + (size_t)row * D_DIM);
    const uint4 v0 = xr[tid], v1 = xr[tid + 256];
    ((uint4*)sx)[tid]       = v0;
    ((uint4*)sx)[tid + 256] = v1;

    if (tid == 0) {
        const float z = ((g_zpart[0][row] + g_zpart[1][row])
                       + (g_zpart[2][row] + g_zpart[3][row])) + b2[0];
        const float sig = 1.0f / (1.0f + expf(-z));
        const float sp  = 0.05f + 0.25f * sig;
        sparsity_out[row] = sp;
        s_k = max(1, (int)rintf((float)D_DIM * (1.0f - sp)));
    }
    __syncthreads();
    const int k = s_k;

    uint32_t prefix = 0;
    int kc = k;
#pragma unroll
    for (int shift = 24; shift >= 0; shift -= 8) {
        hist[tid] = 0;
        __syncthreads();
        const uint32_t himask = (shift == 24) ? 0u : (0xffffffffu << (shift + 8));
        for (int i = tid; i < D_DIM; i += 256) {
            const uint32_t a = sx[i] & 0x7fffffffu;
            const bool pred = (a & himask) == prefix;
            const uint32_t bin = (a >> shift) & 255u;
            const uint32_t key = pred ? bin : 0xffffffffu;
            const uint32_t grpm = __match_any_sync(0xffffffffu, key);
            if (pred && (lane == __ffs(grpm) - 1))
                atomicAdd(&hist[bin], __popc(grpm));
        }
        __syncthreads();
        const uint32_t v = hist[tid];
        uint32_t incl = v;
#pragma unroll
        for (int o = 1; o < 32; o <<= 1) {
            const uint32_t n = __shfl_up_sync(0xffffffffu, incl, o);
            if (lane >= o) incl += n;
        }
        if (lane == 31) uwarp[wid] = incl;
        __syncthreads();
        if (tid == 0) {
            uint32_t a2 = 0;
#pragma unroll
            for (int w = 0; w < 8; w++) { const uint32_t t2 = uwarp[w]; uwarp[w] = a2; a2 += t2; }
        }
        __syncthreads();
        incl += uwarp[wid];
        if ((int)incl >= kc && (int)(incl - v) < kc) {
            s_prefix = prefix | ((uint32_t)tid << shift);
            s_kk = kc - (int)(incl - v);
        }
        __syncthreads();
        prefix = s_prefix;
        kc = s_kk;
        __syncthreads();
    }
    const uint32_t thresh = prefix;

    float asum = 0.0f;
    int cnt = 0;
    {
        const uint32_t u[4] = {v0.x, v0.y, v0.z, v0.w};
        float mm[4], ss[4];
#pragma unroll
        for (int j = 0; j < 4; j++) {
            const uint32_t a = u[j] & 0x7fffffffu;
            const bool m = a > thresh;
            mm[j] = m ? 1.0f : 0.0f;
            ss[j] = m ? __uint_as_float(u[j]) : 0.0f;
            if (m) { cnt++; asum += __uint_as_float(a); }
        }
        const size_t base = (size_t)row * D_DIM + tid * 4;
        *(float4*)(mask_out + base)   = make_float4(mm[0], mm[1], mm[2], mm[3]);
        *(float4*)(sparse_out + base) = make_float4(ss[0], ss[1], ss[2], ss[3]);
    }
    {
        const uint32_t u[4] = {v1.x, v1.y, v1.z, v1.w};
        float mm[4], ss[4];
#pragma unroll
        for (int j = 0; j < 4; j++) {
            const uint32_t a = u[j] & 0x7fffffffu;
            const bool m = a > thresh;
            mm[j] = m ? 1.0f : 0.0f;
            ss[j] = m ? __uint_as_float(u[j]) : 0.0f;
            if (m) { cnt++; asum += __uint_as_float(a); }
        }
        const size_t base = (size_t)row * D_DIM + 1024 + tid * 4;
        *(float4*)(mask_out + base)   = make_float4(mm[0], mm[1], mm[2], mm[3]);
        *(float4*)(sparse_out + base) = make_float4(ss[0], ss[1], ss[2], ss[3]);
    }
#pragma unroll
    for (int o = 16; o > 0; o >>= 1) {
        asum += __shfl_down_sync(0xffffffffu, asum, o);
        cnt  += __shfl_down_sync(0xffffffffu, cnt, o);
    }
    if (lane == 0) { fwarp[wid] = asum; uwarp[wid] = (uint32_t)cnt; }
    __syncthreads();
    if (tid == 0) {
        float ts = 0.0f; int tc = 0;
#pragma unroll
        for (int w = 0; w < 8; w++) { ts += fwarp[w]; tc += (int)uwarp[w]; }
        actsp_out[row] = (float)tc / (float)D_DIM;
        g_rowsum[row] = ts;
    }
}

// ---------------------------------------------------------------------------
// Kernel 3: l1_reg = mean(rowsum)
// ---------------------------------------------------------------------------
__global__ void __launch_bounds__(256)
l1_reduce_kernel(float* __restrict__ out)
{
    __shared__ float red[256];
    const int tid = threadIdx.x;
    float p = 0.0f;
    for (int i = tid; i < B_ROWS; i += 256) p += g_rowsum[i];
    red[tid] = p;
    __syncthreads();
    for (int s = 128; s > 0; s >>= 1) {
        if (tid < s) red[tid] += red[tid + s];
        __syncthreads();
    }
    if (tid == 0) out[0] = red[0] / (float)B_ROWS;
}

// ---------------------------------------------------------------------------
// Launch
// ---------------------------------------------------------------------------
extern "C" void kernel_launch(void* const* d_in, const int* in_sizes, int n_in,
                              void* d_out, int out_size)
{
    const float* X  = (const float*)d_in[0];
    const float* W1 = (const float*)d_in[1];
    const float* b1 = (const float*)d_in[2];
    const float* W2 = (const float*)d_in[3];
    const float* b2 = (const float*)d_in[4];

    float* out = (float*)d_out;
    float* sparse_x = out;
    float* mask     = out + (size_t)B_ROWS * D_DIM;
    float* spars    = out + (size_t)2 * B_ROWS * D_DIM;
    float* actsp    = spars + B_ROWS;
    float* l1       = actsp + B_ROWS;

    cudaFuncSetAttribute(gemm_z_kernel,
                         cudaFuncAttributeMaxDynamicSharedMemorySize, SMEM_BYTES);

    split_w1_kernel<<<dim3(D_DIM / 32, H_DIM / 32), dim3(32, 32)>>>(W1);
    gemm_z_kernel<<<dim3(4, 128), 256, SMEM_BYTES>>>(X, b1, W2);
    select_kernel<<<B_ROWS, 256>>>(X, b2, sparse_x, mask, spars, actsp);
    l1_reduce_kernel<<<1, 256>>>(l1);
}

// round 5
// speedup vs baseline: 1.5462x; 1.0371x over previous
#include <cuda_runtime.h>
#include <cuda_bf16.h>
#include <math.h>
#include <stdint.h>

#define B_ROWS 16384
#define D_DIM  2048
#define H_DIM  512
#define BD ((size_t)B_ROWS * D_DIM)

// ---------------------------------------------------------------------------
// Scratch (device globals; no allocations allowed)
// ---------------------------------------------------------------------------
__device__ __nv_bfloat16 g_xs[3ULL * B_ROWS * D_DIM];   // X 3-way bf16 split (201MB)
__device__ __nv_bfloat16 g_w1s[3][H_DIM][D_DIM];        // W1^T 3-way bf16 split
__device__ float g_zpart[4][B_ROWS];
__device__ int   g_k[B_ROWS];
__device__ float g_rowsum[B_ROWS];
__device__ int   g_nfix;
__device__ int   g_fix[256];
__device__ float g_fixh[256][16][H_DIM];                // repair partial h slices

__device__ __forceinline__ uint32_t pk(__nv_bfloat16 a, __nv_bfloat16 b) {
    return (uint32_t)__bfloat16_as_ushort(a) | ((uint32_t)__bfloat16_as_ushort(b) << 16);
}
__device__ __forceinline__ uint32_t smem_u32(const void* p) {
    uint32_t a;
    asm("{ .reg .u64 t; cvta.to.shared.u64 t, %1; cvt.u32.u64 %0, t; }" : "=r"(a) : "l"(p));
    return a;
}
__device__ __forceinline__ void mma16816(float* c, const uint32_t* a, const uint32_t* b) {
    asm volatile("mma.sync.aligned.m16n8k16.row.col.f32.bf16.bf16.f32 "
                 "{%0,%1,%2,%3}, {%4,%5,%6,%7}, {%8,%9}, {%0,%1,%2,%3};"
                 : "+f"(c[0]), "+f"(c[1]), "+f"(c[2]), "+f"(c[3])
                 : "r"(a[0]), "r"(a[1]), "r"(a[2]), "r"(a[3]), "r"(b[0]), "r"(b[1]));
}
__device__ __forceinline__ void ldsm4(uint32_t& r0, uint32_t& r1, uint32_t& r2,
                                      uint32_t& r3, uint32_t addr) {
    asm volatile("ldmatrix.sync.aligned.m8n8.x4.shared.b16 {%0,%1,%2,%3}, [%4];"
                 : "=r"(r0), "=r"(r1), "=r"(r2), "=r"(r3) : "r"(addr));
}
#define CP16(dst, src) \
    asm volatile("cp.async.cg.shared.global [%0], [%1], 16;" :: "r"(dst), "l"(src))
#define CP_COMMIT() asm volatile("cp.async.commit_group;" ::: "memory")
#define CP_WAIT0()  asm volatile("cp.async.wait_group 0;" ::: "memory")

__device__ __forceinline__ void split3(float x, __nv_bfloat16& s0,
                                       __nv_bfloat16& s1, __nv_bfloat16& s2) {
    s0 = __float2bfloat16_rn(x);
    float r1 = x - __bfloat162float(s0);
    s1 = __float2bfloat16_rn(r1);
    s2 = __float2bfloat16_rn(r1 - __bfloat162float(s1));
}

// ---------------------------------------------------------------------------
// Kernel 0a: split + transpose W1; also resets g_nfix
// ---------------------------------------------------------------------------
__global__ void __launch_bounds__(1024)
split_w1_kernel(const float* __restrict__ W1)
{
    __shared__ float tile[32][33];
    if (blockIdx.x == 0 && blockIdx.y == 0 && threadIdx.x == 0 && threadIdx.y == 0)
        g_nfix = 0;
    const int k0 = blockIdx.x * 32, n0 = blockIdx.y * 32;
    tile[threadIdx.y][threadIdx.x] =
        W1[(size_t)(k0 + threadIdx.y) * H_DIM + n0 + threadIdx.x];
    __syncthreads();
    const float v = tile[threadIdx.x][threadIdx.y];
    const int n = n0 + threadIdx.y, k = k0 + threadIdx.x;
    __nv_bfloat16 s0, s1, s2;
    split3(v, s0, s1, s2);
    g_w1s[0][n][k] = s0; g_w1s[1][n][k] = s1; g_w1s[2][n][k] = s2;
}

// ---------------------------------------------------------------------------
// Kernel 0b: split X -> 3 bf16 planes
// ---------------------------------------------------------------------------
__global__ void __launch_bounds__(256)
split_x_kernel(const float* __restrict__ X)
{
    const size_t i4 = (size_t)blockIdx.x * 256 + threadIdx.x;  // float4 idx
    const float4 v = ((const float4*)X)[i4];
    const float e[4] = {v.x, v.y, v.z, v.w};
    __nv_bfloat16 s0[4], s1[4], s2[4];
#pragma unroll
    for (int j = 0; j < 4; j++) split3(e[j], s0[j], s1[j], s2[j]);
    const size_t eo = i4 * 4;
    *(uint2*)(g_xs + eo)          = make_uint2(pk(s0[0], s0[1]), pk(s0[2], s0[3]));
    *(uint2*)(g_xs + BD + eo)     = make_uint2(pk(s1[0], s1[1]), pk(s1[2], s1[3]));
    *(uint2*)(g_xs + 2 * BD + eo) = make_uint2(pk(s2[0], s2[1]), pk(s2[2], s2[3]));
}

// ---------------------------------------------------------------------------
// Kernel 1: z-partials: 6-term split bf16 mma.sync GEMM, fused relu-dot epilogue
//   SMEM: A tiers [0,30720) B tiers [30720,61440) (80B row stride),
//         b1s 61440, w2s 61952, zred 62464..64512
// ---------------------------------------------------------------------------
#define SMEM_BYTES 64512

__global__ void __launch_bounds__(256, 2)
gemm_z_kernel(const float* __restrict__ b1, const float* __restrict__ W2)
{
    extern __shared__ char sm[];
    float* b1s  = (float*)(sm + 61440);
    float* w2s  = (float*)(sm + 61952);
    float* zred = (float*)(sm + 62464);

    const int tid  = threadIdx.x;
    const int nblk = blockIdx.x;          // fast dim -> 4 CTAs share bm (A L2 reuse)
    const int bn   = nblk * 128;
    const int bm   = blockIdx.y * 128;
    const int warp = tid >> 5, lane = tid & 31;
    const int grp  = lane >> 2, four = lane & 3;
    const int wm   = (warp >> 2) * 64;
    const int wn   = (warp & 3) * 32;
    const uint32_t sb = smem_u32(sm);

    if (tid < 128) { b1s[tid] = b1[bn + tid]; w2s[tid] = W2[bn + tid]; }

    float acc[4][4][4];
#pragma unroll
    for (int mt = 0; mt < 4; mt++)
#pragma unroll
        for (int nt = 0; nt < 4; nt++)
#pragma unroll
            for (int j = 0; j < 4; j++) acc[mt][nt][j] = 0.0f;

    // precompute ldmatrix lane addresses (chunk-invariant parts)
    const int a_row = (lane & 7) + ((lane >> 3) & 1) * 8;     // + wm + mt*16
    const uint32_t a_colb = (uint32_t)(lane >> 4) * 16;       // + ks*32
    const int b_row = (lane & 7) + ((lane >= 16) ? 8 : 0);    // + wn + p*16
    const uint32_t b_colb = (uint32_t)((lane >> 3) & 1) * 16; // + ks*32

    for (int kc = 0; kc < 64; kc++) {
        // ---- cp.async A (3 tiers x 128 x 32 bf16) and B
#pragma unroll
        for (int i = 0; i < 6; i++) {
            const int f = i * 256 + tid;
            const int s = f >> 9, rem = f & 511;
            const int r = rem >> 2, slot = rem & 3;
            const __nv_bfloat16* src =
                g_xs + (size_t)s * BD + (size_t)(bm + r) * D_DIM + kc * 32 + slot * 8;
            CP16(sb + s * 10240 + r * 80 + slot * 16, src);
        }
#pragma unroll
        for (int i = 0; i < 6; i++) {
            const int f = i * 256 + tid;
            const int s = f >> 9, rem = f & 511;
            const int r = rem >> 2, slot = rem & 3;
            const __nv_bfloat16* src = &g_w1s[s][bn + r][kc * 32 + slot * 8];
            CP16(sb + 30720 + s * 10240 + r * 80 + slot * 16, src);
        }
        CP_COMMIT();
        CP_WAIT0();
        __syncthreads();

#pragma unroll
        for (int ks = 0; ks < 2; ks++) {
            uint32_t bf[3][4][2];
#pragma unroll
            for (int s = 0; s < 3; s++)
#pragma unroll
                for (int p = 0; p < 2; p++) {
                    const uint32_t ad = sb + 30720 + s * 10240
                                      + (wn + p * 16 + b_row) * 80 + ks * 32 + b_colb;
                    ldsm4(bf[s][2 * p][0], bf[s][2 * p][1],
                          bf[s][2 * p + 1][0], bf[s][2 * p + 1][1], ad);
                }
#pragma unroll
            for (int mt = 0; mt < 4; mt++) {
                uint32_t af[3][4];
#pragma unroll
                for (int s = 0; s < 3; s++) {
                    const uint32_t ad = sb + s * 10240
                                      + (wm + mt * 16 + a_row) * 80 + ks * 32 + a_colb;
                    ldsm4(af[s][0], af[s][1], af[s][2], af[s][3], ad);
                }
#pragma unroll
                for (int nt = 0; nt < 4; nt++) {
                    mma16816(acc[mt][nt], af[0], bf[0][nt]);
                    mma16816(acc[mt][nt], af[1], bf[0][nt]);
                    mma16816(acc[mt][nt], af[0], bf[1][nt]);
                    mma16816(acc[mt][nt], af[1], bf[1][nt]);
                    mma16816(acc[mt][nt], af[2], bf[0][nt]);
                    mma16816(acc[mt][nt], af[0], bf[2][nt]);
                }
            }
        }
        __syncthreads();
    }

    // ---- epilogue: zpart[row] = sum_n relu(c+b1)*w2
#pragma unroll
    for (int mt = 0; mt < 4; mt++) {
        float p0 = 0.0f, p1 = 0.0f;
#pragma unroll
        for (int nt = 0; nt < 4; nt++) {
            const int n0 = wn + nt * 8 + four * 2;
            p0 = fmaf(fmaxf(acc[mt][nt][0] + b1s[n0], 0.0f),     w2s[n0],     p0);
            p0 = fmaf(fmaxf(acc[mt][nt][1] + b1s[n0 + 1], 0.0f), w2s[n0 + 1], p0);
            p1 = fmaf(fmaxf(acc[mt][nt][2] + b1s[n0], 0.0f),     w2s[n0],     p1);
            p1 = fmaf(fmaxf(acc[mt][nt][3] + b1s[n0 + 1], 0.0f), w2s[n0 + 1], p1);
        }
        p0 += __shfl_xor_sync(0xffffffffu, p0, 1);
        p0 += __shfl_xor_sync(0xffffffffu, p0, 2);
        p1 += __shfl_xor_sync(0xffffffffu, p1, 1);
        p1 += __shfl_xor_sync(0xffffffffu, p1, 2);
        if (four == 0) {
            zred[(warp & 3) * 128 + wm + mt * 16 + grp]     = p0;
            zred[(warp & 3) * 128 + wm + mt * 16 + grp + 8] = p1;
        }
    }
    __syncthreads();
    if (tid < 128) {
        const float z = (zred[tid] + zred[128 + tid]) + (zred[256 + tid] + zred[384 + tid]);
        g_zpart[nblk][bm + tid] = z;
    }
}

// ---------------------------------------------------------------------------
// Kernel 2: z -> sigmoid -> sparsity -> k; flag rows near rounding boundary
// ---------------------------------------------------------------------------
__global__ void __launch_bounds__(256)
kprep_kernel(const float* __restrict__ b2, float* __restrict__ sparsity_out)
{
    const int row = blockIdx.x * 256 + threadIdx.x;
    const float z = ((g_zpart[0][row] + g_zpart[1][row])
                   + (g_zpart[2][row] + g_zpart[3][row])) + b2[0];
    const float sig = 1.0f / (1.0f + expf(-z));
    const float sp  = 0.05f + 0.25f * sig;
    const float arg = (float)D_DIM * (1.0f - sp);
    sparsity_out[row] = sp;
    g_k[row] = max(1, (int)rintf(arg));
    const float fr = arg - floorf(arg);
    if (fabsf(fr - 0.5f) < 2e-3f) {
        const int i = atomicAdd(&g_nfix, 1);
        if (i < 256) g_fix[i] = row;
    }
}

// ---------------------------------------------------------------------------
// Kernel 3a/3b: exact fp32 repair of flagged rows (deterministic)
// ---------------------------------------------------------------------------
__global__ void __launch_bounds__(256)
repair1_kernel(const float* __restrict__ X, const float* __restrict__ W1)
{
    const int slot = blockIdx.x;
    if (slot >= g_nfix || slot >= 256) return;
    const int ks = blockIdx.y;             // 16 slices x 128 k
    const int row = g_fix[slot];
    __shared__ float xs[128];
    const int tid = threadIdx.x;
    if (tid < 32)
        ((float4*)xs)[tid] = ((const float4*)(X + (size_t)row * D_DIM + ks * 128))[tid];
    __syncthreads();
    float a0 = 0.0f, a1 = 0.0f;
    const float* wp = W1 + (size_t)(ks * 128) * H_DIM;
#pragma unroll 4
    for (int kk = 0; kk < 128; kk++) {
        const float xv = xs[kk];
        a0 = fmaf(xv, wp[(size_t)kk * H_DIM + tid], a0);
        a1 = fmaf(xv, wp[(size_t)kk * H_DIM + tid + 256], a1);
    }
    g_fixh[slot][ks][tid]       = a0;
    g_fixh[slot][ks][tid + 256] = a1;
}

__global__ void __launch_bounds__(256)
repair2_kernel(const float* __restrict__ b1, const float* __restrict__ W2,
               const float* __restrict__ b2, float* __restrict__ sparsity_out)
{
    const int slot = blockIdx.x;
    if (slot >= g_nfix || slot >= 256) return;
    const int row = g_fix[slot];
    const int tid = threadIdx.x;
    __shared__ float red[256];
    float p = 0.0f;
#pragma unroll
    for (int c = 0; c < 2; c++) {
        const int n = tid + c * 256;
        float h = 0.0f;
#pragma unroll
        for (int s = 0; s < 16; s++) h += g_fixh[slot][s][n];
        p = fmaf(fmaxf(h + b1[n], 0.0f), W2[n], p);
    }
    red[tid] = p;
    __syncthreads();
    for (int s = 128; s > 0; s >>= 1) {
        if (tid < s) red[tid] += red[tid + s];
        __syncthreads();
    }
    if (tid == 0) {
        const float z = red[0] + b2[0];
        const float sig = 1.0f / (1.0f + expf(-z));
        const float sp  = 0.05f + 0.25f * sig;
        sparsity_out[row] = sp;
        g_k[row] = max(1, (int)rintf((float)D_DIM * (1.0f - sp)));
    }
}

// ---------------------------------------------------------------------------
// Kernel 4: exact k-th |x|: 1 hist pass (top-11-bit bins) + candidate rank select
// ---------------------------------------------------------------------------
__global__ void __launch_bounds__(256)
select_kernel(const float* __restrict__ X,
              float* __restrict__ sparse_out,
              float* __restrict__ mask_out,
              float* __restrict__ actsp_out)
{
    __shared__ int      hist[2048];
    __shared__ uint32_t cand[1024];
    __shared__ int      warpsum[8];
    __shared__ float    fwarp[8];
    __shared__ int      iwarp[8];
    __shared__ int      s_bin, s_kp, s_cnt;
    __shared__ uint32_t s_thresh;

    const int row = blockIdx.x, tid = threadIdx.x;
    const int lane = tid & 31, wid = tid >> 5;
    const uint4* xr = (const uint4*)(X + (size_t)row * D_DIM);
    const uint4 v0 = xr[tid], v1 = xr[tid + 256];
    uint32_t e[8] = {v0.x, v0.y, v0.z, v0.w, v1.x, v1.y, v1.z, v1.w};
    const int k = g_k[row];

#pragma unroll
    for (int i = 0; i < 8; i++) hist[tid + i * 256] = 0;
    if (tid == 0) s_cnt = 0;
    __syncthreads();

    // histogram on top 11 bits of |x| bit pattern (warp-aggregated)
#pragma unroll
    for (int j = 0; j < 8; j++) {
        const uint32_t bin = (e[j] & 0x7fffffffu) >> 20;
        const uint32_t grpm = __match_any_sync(0xffffffffu, bin);
        if (lane == (int)__ffs(grpm) - 1) atomicAdd(&hist[bin], __popc(grpm));
    }
    __syncthreads();

    // block scan over 2048 bins; locate target bin + rank within
    int cv[8], run = 0;
#pragma unroll
    for (int j = 0; j < 8; j++) { run += hist[tid * 8 + j]; cv[j] = run; }
    const int tot = run;
    int incl = tot;
#pragma unroll
    for (int o = 1; o < 32; o <<= 1) {
        const int n = __shfl_up_sync(0xffffffffu, incl, o);
        if (lane >= o) incl += n;
    }
    if (lane == 31) warpsum[wid] = incl;
    __syncthreads();
    if (tid == 0) {
        int a = 0;
#pragma unroll
        for (int w = 0; w < 8; w++) { const int t = warpsum[w]; warpsum[w] = a; a += t; }
    }
    __syncthreads();
    const int excl = incl - tot + warpsum[wid];
    if (k > excl && k <= excl + tot) {
#pragma unroll
        for (int j = 0; j < 8; j++) {
            const int prev = (j == 0) ? 0 : cv[j - 1];
            if (k > excl + prev && k <= excl + cv[j]) {
                s_bin = tid * 8 + j;
                s_kp  = k - (excl + prev);
            }
        }
    }
    __syncthreads();
    const uint32_t tbin = (uint32_t)s_bin;
    const int kp = s_kp;

    // collect candidates in the target bin
#pragma unroll
    for (int j = 0; j < 8; j++) {
        const uint32_t a = e[j] & 0x7fffffffu;
        if ((a >> 20) == tbin) {
            const int pos = atomicAdd(&s_cnt, 1);
            cand[pos & 1023] = a;
        }
    }
    __syncthreads();
    const int C = s_cnt;

    // rank select among candidates (broadcast inner loop)
    for (int ci = tid; ci < C; ci += 256) {
        const uint32_t v = cand[ci];
        int lt = 0, eq = 0;
        for (int j = 0; j < C; j++) {
            const uint32_t w = cand[j];
            lt += (w < v);
            eq += (w == v);
        }
        if (lt < kp && kp <= lt + eq) s_thresh = v;
    }
    __syncthreads();
    const uint32_t thresh = s_thresh;

    // outputs from registers
    float asum = 0.0f;
    int cnt = 0;
#pragma unroll
    for (int half = 0; half < 2; half++) {
        float mm[4], ss[4];
#pragma unroll
        for (int j = 0; j < 4; j++) {
            const uint32_t u = e[half * 4 + j];
            const uint32_t a = u & 0x7fffffffu;
            const bool m = a > thresh;
            mm[j] = m ? 1.0f : 0.0f;
            ss[j] = m ? __uint_as_float(u) : 0.0f;
            if (m) { cnt++; asum += __uint_as_float(a); }
        }
        const size_t base = (size_t)row * D_DIM + half * 1024 + tid * 4;
        *(float4*)(mask_out + base)   = make_float4(mm[0], mm[1], mm[2], mm[3]);
        *(float4*)(sparse_out + base) = make_float4(ss[0], ss[1], ss[2], ss[3]);
    }
#pragma unroll
    for (int o = 16; o > 0; o >>= 1) {
        asum += __shfl_down_sync(0xffffffffu, asum, o);
        cnt  += __shfl_down_sync(0xffffffffu, cnt, o);
    }
    if (lane == 0) { fwarp[wid] = asum; iwarp[wid] = cnt; }
    __syncthreads();
    if (tid == 0) {
        float ts = 0.0f; int tc = 0;
#pragma unroll
        for (int w = 0; w < 8; w++) { ts += fwarp[w]; tc += iwarp[w]; }
        actsp_out[row] = (float)tc / (float)D_DIM;
        g_rowsum[row] = ts;
    }
}

// ---------------------------------------------------------------------------
// Kernel 5: l1_reg = mean(rowsum)
// ---------------------------------------------------------------------------
__global__ void __launch_bounds__(256)
l1_reduce_kernel(float* __restrict__ out)
{
    __shared__ float red[256];
    const int tid = threadIdx.x;
    float p = 0.0f;
    for (int i = tid; i < B_ROWS; i += 256) p += g_rowsum[i];
    red[tid] = p;
    __syncthreads();
    for (int s = 128; s > 0; s >>= 1) {
        if (tid < s) red[tid] += red[tid + s];
        __syncthreads();
    }
    if (tid == 0) out[0] = red[0] / (float)B_ROWS;
}

// ---------------------------------------------------------------------------
// Launch
// ---------------------------------------------------------------------------
extern "C" void kernel_launch(void* const* d_in, const int* in_sizes, int n_in,
                              void* d_out, int out_size)
{
    const float* X  = (const float*)d_in[0];
    const float* W1 = (const float*)d_in[1];
    const float* b1 = (const float*)d_in[2];
    const float* W2 = (const float*)d_in[3];
    const float* b2 = (const float*)d_in[4];

    float* out = (float*)d_out;
    float* sparse_x = out;
    float* mask     = out + BD;
    float* spars    = out + 2 * BD;
    float* actsp    = spars + B_ROWS;
    float* l1       = actsp + B_ROWS;

    cudaFuncSetAttribute(gemm_z_kernel,
                         cudaFuncAttributeMaxDynamicSharedMemorySize, SMEM_BYTES);

    split_w1_kernel<<<dim3(D_DIM / 32, H_DIM / 32), dim3(32, 32)>>>(W1);
    split_x_kernel<<<(int)(BD / 4 / 256), 256>>>(X);
    gemm_z_kernel<<<dim3(4, 128), 256, SMEM_BYTES>>>(b1, W2);
    kprep_kernel<<<B_ROWS / 256, 256>>>(b2, spars);
    repair1_kernel<<<dim3(256, 16), 256>>>(X, W1);
    repair2_kernel<<<256, 256>>>(b1, W2, b2, spars);
    select_kernel<<<B_ROWS, 256>>>(X, sparse_x, mask, actsp);
    l1_reduce_kernel<<<1, 256>>>(l1);
}

// round 6
// speedup vs baseline: 1.8302x; 1.1837x over previous
#include <cuda_runtime.h>
#include <cuda_bf16.h>
#include <math.h>
#include <stdint.h>

#define B_ROWS 16384
#define D_DIM  2048
#define H_DIM  512
#define BD ((size_t)B_ROWS * D_DIM)
#define NFIX_MAX 1024

// ---------------------------------------------------------------------------
// Scratch (device globals; no allocations allowed)
// ---------------------------------------------------------------------------
__device__ __nv_bfloat16 g_xs[2ULL * B_ROWS * D_DIM];   // X 2-tier bf16 split
__device__ __nv_bfloat16 g_w1s[2][H_DIM][D_DIM];        // W1^T 2-tier bf16 split
__device__ float g_zpart[4][B_ROWS];
__device__ int   g_k[B_ROWS];
__device__ float g_rowsum[B_ROWS];
__device__ int   g_nfix;
__device__ int   g_fix[NFIX_MAX];
__device__ float g_fixh[NFIX_MAX][16][H_DIM];           // repair partial h slices

__device__ __forceinline__ uint32_t pk(__nv_bfloat16 a, __nv_bfloat16 b) {
    return (uint32_t)__bfloat16_as_ushort(a) | ((uint32_t)__bfloat16_as_ushort(b) << 16);
}
__device__ __forceinline__ uint32_t smem_u32(const void* p) {
    uint32_t a;
    asm("{ .reg .u64 t; cvta.to.shared.u64 t, %1; cvt.u32.u64 %0, t; }" : "=r"(a) : "l"(p));
    return a;
}
__device__ __forceinline__ void mma16816(float* c, const uint32_t* a, const uint32_t* b) {
    asm volatile("mma.sync.aligned.m16n8k16.row.col.f32.bf16.bf16.f32 "
                 "{%0,%1,%2,%3}, {%4,%5,%6,%7}, {%8,%9}, {%0,%1,%2,%3};"
                 : "+f"(c[0]), "+f"(c[1]), "+f"(c[2]), "+f"(c[3])
                 : "r"(a[0]), "r"(a[1]), "r"(a[2]), "r"(a[3]), "r"(b[0]), "r"(b[1]));
}
__device__ __forceinline__ void ldsm4(uint32_t& r0, uint32_t& r1, uint32_t& r2,
                                      uint32_t& r3, uint32_t addr) {
    asm volatile("ldmatrix.sync.aligned.m8n8.x4.shared.b16 {%0,%1,%2,%3}, [%4];"
                 : "=r"(r0), "=r"(r1), "=r"(r2), "=r"(r3) : "r"(addr));
}
#define CP16(dst, src) \
    asm volatile("cp.async.cg.shared.global [%0], [%1], 16;" :: "r"(dst), "l"(src))
#define CP_COMMIT()  asm volatile("cp.async.commit_group;" ::: "memory")
#define CP_WAIT(n)   asm volatile("cp.async.wait_group %0;" :: "n"(n) : "memory")

__device__ __forceinline__ void split2(float x, __nv_bfloat16& s0, __nv_bfloat16& s1) {
    s0 = __float2bfloat16_rn(x);
    s1 = __float2bfloat16_rn(x - __bfloat162float(s0));
}

// ---------------------------------------------------------------------------
// Kernel 0a: split + transpose W1 (2 tiers); resets g_nfix
// ---------------------------------------------------------------------------
__global__ void __launch_bounds__(1024)
split_w1_kernel(const float* __restrict__ W1)
{
    __shared__ float tile[32][33];
    if (blockIdx.x == 0 && blockIdx.y == 0 && threadIdx.x == 0 && threadIdx.y == 0)
        g_nfix = 0;
    const int k0 = blockIdx.x * 32, n0 = blockIdx.y * 32;
    tile[threadIdx.y][threadIdx.x] =
        W1[(size_t)(k0 + threadIdx.y) * H_DIM + n0 + threadIdx.x];
    __syncthreads();
    const float v = tile[threadIdx.x][threadIdx.y];
    const int n = n0 + threadIdx.y, k = k0 + threadIdx.x;
    __nv_bfloat16 s0, s1;
    split2(v, s0, s1);
    g_w1s[0][n][k] = s0;
    g_w1s[1][n][k] = s1;
}

// ---------------------------------------------------------------------------
// Kernel 0b: split X -> 2 bf16 planes
// ---------------------------------------------------------------------------
__global__ void __launch_bounds__(256)
split_x_kernel(const float* __restrict__ X)
{
    const size_t i4 = (size_t)blockIdx.x * 256 + threadIdx.x;
    const float4 v = ((const float4*)X)[i4];
    const float e[4] = {v.x, v.y, v.z, v.w};
    __nv_bfloat16 s0[4], s1[4];
#pragma unroll
    for (int j = 0; j < 4; j++) split2(e[j], s0[j], s1[j]);
    const size_t eo = i4 * 4;
    *(uint2*)(g_xs + eo)      = make_uint2(pk(s0[0], s0[1]), pk(s0[2], s0[3]));
    *(uint2*)(g_xs + BD + eo) = make_uint2(pk(s1[0], s1[1]), pk(s1[2], s1[3]));
}

// ---------------------------------------------------------------------------
// Kernel 1: z-partials: 3-term split bf16 mma.sync GEMM, 2-stage cp.async
//   pipeline, fused relu-dot epilogue.
//   SMEM per stage (40960B): A0 A1 B0 B1, each 128 rows x 80B (32 bf16 + pad).
//   stage0 @0, stage1 @40960; b1s @81920, w2s @82432, zred @82944..84992
// ---------------------------------------------------------------------------
#define STG 40960
#define SMEM_BYTES 84992

__global__ void __launch_bounds__(256, 2)
gemm_z_kernel(const float* __restrict__ b1, const float* __restrict__ W2)
{
    extern __shared__ char sm[];
    float* b1s  = (float*)(sm + 81920);
    float* w2s  = (float*)(sm + 82432);
    float* zred = (float*)(sm + 82944);

    const int tid  = threadIdx.x;
    const int nblk = blockIdx.x;
    const int bn   = nblk * 128;
    const int bm   = blockIdx.y * 128;
    const int warp = tid >> 5, lane = tid & 31;
    const int grp  = lane >> 2, four = lane & 3;
    const int wm   = (warp >> 2) * 64;
    const int wn   = (warp & 3) * 32;
    const uint32_t sb = smem_u32(sm);

    if (tid < 128) { b1s[tid] = b1[bn + tid]; w2s[tid] = W2[bn + tid]; }

    float acc[4][4][4];
#pragma unroll
    for (int mt = 0; mt < 4; mt++)
#pragma unroll
        for (int nt = 0; nt < 4; nt++)
#pragma unroll
            for (int j = 0; j < 4; j++) acc[mt][nt][j] = 0.0f;

    // per-thread load slots: 8 x 16B per stage (A 2 tiers + B 2 tiers)
    //   f = i*256+tid over 1024 -> tier s = f>>9, row r = (f&511)>>2, slot = f&3
    const int l_s = tid >> 1;                 // reuse pattern below instead
    (void)l_s;

    // ldmatrix lane addressing (chunk-invariant)
    const int a_row = (lane & 7) + ((lane >> 3) & 1) * 8;
    const uint32_t a_colb = (uint32_t)(lane >> 4) * 16;
    const int b_row = (lane & 7) + ((lane >= 16) ? 8 : 0);
    const uint32_t b_colb = (uint32_t)((lane >> 3) & 1) * 16;

    // issue loads for chunk kc into stage buffer st
    auto issue_loads = [&](int kc, int st) {
        const uint32_t base = sb + st * STG;
#pragma unroll
        for (int i = 0; i < 4; i++) {           // A: 2 tiers x 512 chunks
            const int f = i * 256 + tid;
            const int s = f >> 9, rem = f & 511;
            const int r = rem >> 2, slot = rem & 3;
            const __nv_bfloat16* src =
                g_xs + (size_t)s * BD + (size_t)(bm + r) * D_DIM + kc * 32 + slot * 8;
            CP16(base + s * 10240 + r * 80 + slot * 16, src);
        }
#pragma unroll
        for (int i = 0; i < 4; i++) {           // B: 2 tiers
            const int f = i * 256 + tid;
            const int s = f >> 9, rem = f & 511;
            const int r = rem >> 2, slot = rem & 3;
            const __nv_bfloat16* src = &g_w1s[s][bn + r][kc * 32 + slot * 8];
            CP16(base + 20480 + s * 10240 + r * 80 + slot * 16, src);
        }
        CP_COMMIT();
    };

    issue_loads(0, 0);

    for (int kc = 0; kc < 64; kc++) {
        const int st = kc & 1;
        if (kc + 1 < 64) {
            issue_loads(kc + 1, (kc + 1) & 1);
            CP_WAIT(1);
        } else {
            CP_WAIT(0);
        }
        __syncthreads();

        const uint32_t abase = sb + st * STG;
        const uint32_t bbase = abase + 20480;
#pragma unroll
        for (int ks = 0; ks < 2; ks++) {
            uint32_t bf[2][4][2];
#pragma unroll
            for (int s = 0; s < 2; s++)
#pragma unroll
                for (int p = 0; p < 2; p++) {
                    const uint32_t ad = bbase + s * 10240
                                      + (wn + p * 16 + b_row) * 80 + ks * 32 + b_colb;
                    ldsm4(bf[s][2 * p][0], bf[s][2 * p][1],
                          bf[s][2 * p + 1][0], bf[s][2 * p + 1][1], ad);
                }
#pragma unroll
            for (int mt = 0; mt < 4; mt++) {
                uint32_t af[2][4];
#pragma unroll
                for (int s = 0; s < 2; s++) {
                    const uint32_t ad = abase + s * 10240
                                      + (wm + mt * 16 + a_row) * 80 + ks * 32 + a_colb;
                    ldsm4(af[s][0], af[s][1], af[s][2], af[s][3], ad);
                }
#pragma unroll
                for (int nt = 0; nt < 4; nt++) {
                    mma16816(acc[mt][nt], af[0], bf[0][nt]);
                    mma16816(acc[mt][nt], af[1], bf[0][nt]);
                    mma16816(acc[mt][nt], af[0], bf[1][nt]);
                }
            }
        }
        __syncthreads();
    }

    // ---- epilogue: zpart[row] = sum_n relu(c+b1)*w2
#pragma unroll
    for (int mt = 0; mt < 4; mt++) {
        float p0 = 0.0f, p1 = 0.0f;
#pragma unroll
        for (int nt = 0; nt < 4; nt++) {
            const int n0 = wn + nt * 8 + four * 2;
            p0 = fmaf(fmaxf(acc[mt][nt][0] + b1s[n0], 0.0f),     w2s[n0],     p0);
            p0 = fmaf(fmaxf(acc[mt][nt][1] + b1s[n0 + 1], 0.0f), w2s[n0 + 1], p0);
            p1 = fmaf(fmaxf(acc[mt][nt][2] + b1s[n0], 0.0f),     w2s[n0],     p1);
            p1 = fmaf(fmaxf(acc[mt][nt][3] + b1s[n0 + 1], 0.0f), w2s[n0 + 1], p1);
        }
        p0 += __shfl_xor_sync(0xffffffffu, p0, 1);
        p0 += __shfl_xor_sync(0xffffffffu, p0, 2);
        p1 += __shfl_xor_sync(0xffffffffu, p1, 1);
        p1 += __shfl_xor_sync(0xffffffffu, p1, 2);
        if (four == 0) {
            zred[(warp & 3) * 128 + wm + mt * 16 + grp]     = p0;
            zred[(warp & 3) * 128 + wm + mt * 16 + grp + 8] = p1;
        }
    }
    __syncthreads();
    if (tid < 128) {
        const float z = (zred[tid] + zred[128 + tid]) + (zred[256 + tid] + zred[384 + tid]);
        g_zpart[nblk][bm + tid] = z;
    }
}

// ---------------------------------------------------------------------------
// Kernel 2: z -> sigmoid -> sparsity -> k; flag rows near rounding boundary
// ---------------------------------------------------------------------------
__global__ void __launch_bounds__(256)
kprep_kernel(const float* __restrict__ b2, float* __restrict__ sparsity_out)
{
    const int row = blockIdx.x * 256 + threadIdx.x;
    const float z = ((g_zpart[0][row] + g_zpart[1][row])
                   + (g_zpart[2][row] + g_zpart[3][row])) + b2[0];
    const float sig = 1.0f / (1.0f + expf(-z));
    const float sp  = 0.05f + 0.25f * sig;
    const float arg = (float)D_DIM * (1.0f - sp);
    sparsity_out[row] = sp;
    g_k[row] = max(1, (int)rintf(arg));
    const float fr = arg - floorf(arg);
    if (fabsf(fr - 0.5f) < 0.02f) {
        const int i = atomicAdd(&g_nfix, 1);
        if (i < NFIX_MAX) g_fix[i] = row;
    }
}

// ---------------------------------------------------------------------------
// Kernel 3a/3b: exact fp32 repair of flagged rows (deterministic)
// ---------------------------------------------------------------------------
__global__ void __launch_bounds__(256)
repair1_kernel(const float* __restrict__ X, const float* __restrict__ W1)
{
    const int slot = blockIdx.x;
    if (slot >= g_nfix || slot >= NFIX_MAX) return;
    const int ks = blockIdx.y;
    const int row = g_fix[slot];
    __shared__ float xs[128];
    const int tid = threadIdx.x;
    if (tid < 32)
        ((float4*)xs)[tid] = ((const float4*)(X + (size_t)row * D_DIM + ks * 128))[tid];
    __syncthreads();
    float a0 = 0.0f, a1 = 0.0f;
    const float* wp = W1 + (size_t)(ks * 128) * H_DIM;
#pragma unroll 4
    for (int kk = 0; kk < 128; kk++) {
        const float xv = xs[kk];
        a0 = fmaf(xv, wp[(size_t)kk * H_DIM + tid], a0);
        a1 = fmaf(xv, wp[(size_t)kk * H_DIM + tid + 256], a1);
    }
    g_fixh[slot][ks][tid]       = a0;
    g_fixh[slot][ks][tid + 256] = a1;
}

__global__ void __launch_bounds__(256)
repair2_kernel(const float* __restrict__ b1, const float* __restrict__ W2,
               const float* __restrict__ b2, float* __restrict__ sparsity_out)
{
    const int slot = blockIdx.x;
    if (slot >= g_nfix || slot >= NFIX_MAX) return;
    const int row = g_fix[slot];
    const int tid = threadIdx.x;
    __shared__ float red[256];
    float p = 0.0f;
#pragma unroll
    for (int c = 0; c < 2; c++) {
        const int n = tid + c * 256;
        float h = 0.0f;
#pragma unroll
        for (int s = 0; s < 16; s++) h += g_fixh[slot][s][n];
        p = fmaf(fmaxf(h + b1[n], 0.0f), W2[n], p);
    }
    red[tid] = p;
    __syncthreads();
    for (int s = 128; s > 0; s >>= 1) {
        if (tid < s) red[tid] += red[tid + s];
        __syncthreads();
    }
    if (tid == 0) {
        const float z = red[0] + b2[0];
        const float sig = 1.0f / (1.0f + expf(-z));
        const float sp  = 0.05f + 0.25f * sig;
        sparsity_out[row] = sp;
        g_k[row] = max(1, (int)rintf((float)D_DIM * (1.0f - sp)));
    }
}

// ---------------------------------------------------------------------------
// Kernel 4: exact k-th |x|: 1 hist pass (top-11-bit bins) + candidate rank select
// ---------------------------------------------------------------------------
__global__ void __launch_bounds__(256)
select_kernel(const float* __restrict__ X,
              float* __restrict__ sparse_out,
              float* __restrict__ mask_out,
              float* __restrict__ actsp_out)
{
    __shared__ int      hist[2048];
    __shared__ uint32_t cand[1024];
    __shared__ int      warpsum[8];
    __shared__ float    fwarp[8];
    __shared__ int      iwarp[8];
    __shared__ int      s_bin, s_kp, s_cnt;
    __shared__ uint32_t s_thresh;

    const int row = blockIdx.x, tid = threadIdx.x;
    const int lane = tid & 31, wid = tid >> 5;
    const uint4* xr = (const uint4*)(X + (size_t)row * D_DIM);
    const uint4 v0 = xr[tid], v1 = xr[tid + 256];
    uint32_t e[8] = {v0.x, v0.y, v0.z, v0.w, v1.x, v1.y, v1.z, v1.w};
    const int k = g_k[row];

#pragma unroll
    for (int i = 0; i < 8; i++) hist[tid + i * 256] = 0;
    if (tid == 0) s_cnt = 0;
    __syncthreads();

#pragma unroll
    for (int j = 0; j < 8; j++) {
        const uint32_t bin = (e[j] & 0x7fffffffu) >> 20;
        const uint32_t grpm = __match_any_sync(0xffffffffu, bin);
        if (lane == (int)__ffs(grpm) - 1) atomicAdd(&hist[bin], __popc(grpm));
    }
    __syncthreads();

    int cv[8], run = 0;
#pragma unroll
    for (int j = 0; j < 8; j++) { run += hist[tid * 8 + j]; cv[j] = run; }
    const int tot = run;
    int incl = tot;
#pragma unroll
    for (int o = 1; o < 32; o <<= 1) {
        const int n = __shfl_up_sync(0xffffffffu, incl, o);
        if (lane >= o) incl += n;
    }
    if (lane == 31) warpsum[wid] = incl;
    __syncthreads();
    if (tid == 0) {
        int a = 0;
#pragma unroll
        for (int w = 0; w < 8; w++) { const int t = warpsum[w]; warpsum[w] = a; a += t; }
    }
    __syncthreads();
    const int excl = incl - tot + warpsum[wid];
    if (k > excl && k <= excl + tot) {
#pragma unroll
        for (int j = 0; j < 8; j++) {
            const int prev = (j == 0) ? 0 : cv[j - 1];
            if (k > excl + prev && k <= excl + cv[j]) {
                s_bin = tid * 8 + j;
                s_kp  = k - (excl + prev);
            }
        }
    }
    __syncthreads();
    const uint32_t tbin = (uint32_t)s_bin;
    const int kp = s_kp;

#pragma unroll
    for (int j = 0; j < 8; j++) {
        const uint32_t a = e[j] & 0x7fffffffu;
        if ((a >> 20) == tbin) {
            const int pos = atomicAdd(&s_cnt, 1);
            cand[pos & 1023] = a;
        }
    }
    __syncthreads();
    const int C = s_cnt;

    for (int ci = tid; ci < C; ci += 256) {
        const uint32_t v = cand[ci];
        int lt = 0, eq = 0;
        for (int j = 0; j < C; j++) {
            const uint32_t w = cand[j];
            lt += (w < v);
            eq += (w == v);
        }
        if (lt < kp && kp <= lt + eq) s_thresh = v;
    }
    __syncthreads();
    const uint32_t thresh = s_thresh;

    float asum = 0.0f;
    int cnt = 0;
#pragma unroll
    for (int half = 0; half < 2; half++) {
        float mm[4], ss[4];
#pragma unroll
        for (int j = 0; j < 4; j++) {
            const uint32_t u = e[half * 4 + j];
            const uint32_t a = u & 0x7fffffffu;
            const bool m = a > thresh;
            mm[j] = m ? 1.0f : 0.0f;
            ss[j] = m ? __uint_as_float(u) : 0.0f;
            if (m) { cnt++; asum += __uint_as_float(a); }
        }
        const size_t base = (size_t)row * D_DIM + half * 1024 + tid * 4;
        *(float4*)(mask_out + base)   = make_float4(mm[0], mm[1], mm[2], mm[3]);
        *(float4*)(sparse_out + base) = make_float4(ss[0], ss[1], ss[2], ss[3]);
    }
#pragma unroll
    for (int o = 16; o > 0; o >>= 1) {
        asum += __shfl_down_sync(0xffffffffu, asum, o);
        cnt  += __shfl_down_sync(0xffffffffu, cnt, o);
    }
    if (lane == 0) { fwarp[wid] = asum; iwarp[wid] = cnt; }
    __syncthreads();
    if (tid == 0) {
        float ts = 0.0f; int tc = 0;
#pragma unroll
        for (int w = 0; w < 8; w++) { ts += fwarp[w]; tc += iwarp[w]; }
        actsp_out[row] = (float)tc / (float)D_DIM;
        g_rowsum[row] = ts;
    }
}

// ---------------------------------------------------------------------------
// Kernel 5: l1_reg = mean(rowsum)
// ---------------------------------------------------------------------------
__global__ void __launch_bounds__(256)
l1_reduce_kernel(float* __restrict__ out)
{
    __shared__ float red[256];
    const int tid = threadIdx.x;
    float p = 0.0f;
    for (int i = tid; i < B_ROWS; i += 256) p += g_rowsum[i];
    red[tid] = p;
    __syncthreads();
    for (int s = 128; s > 0; s >>= 1) {
        if (tid < s) red[tid] += red[tid + s];
        __syncthreads();
    }
    if (tid == 0) out[0] = red[0] / (float)B_ROWS;
}

// ---------------------------------------------------------------------------
// Launch
// ---------------------------------------------------------------------------
extern "C" void kernel_launch(void* const* d_in, const int* in_sizes, int n_in,
                              void* d_out, int out_size)
{
    const float* X  = (const float*)d_in[0];
    const float* W1 = (const float*)d_in[1];
    const float* b1 = (const float*)d_in[2];
    const float* W2 = (const float*)d_in[3];
    const float* b2 = (const float*)d_in[4];

    float* out = (float*)d_out;
    float* sparse_x = out;
    float* mask     = out + BD;
    float* spars    = out + 2 * BD;
    float* actsp    = spars + B_ROWS;
    float* l1       = actsp + B_ROWS;

    cudaFuncSetAttribute(gemm_z_kernel,
                         cudaFuncAttributeMaxDynamicSharedMemorySize, SMEM_BYTES);

    split_w1_kernel<<<dim3(D_DIM / 32, H_DIM / 32), dim3(32, 32)>>>(W1);
    split_x_kernel<<<(int)(BD / 4 / 256), 256>>>(X);
    gemm_z_kernel<<<dim3(4, 128), 256, SMEM_BYTES>>>(b1, W2);
    kprep_kernel<<<B_ROWS / 256, 256>>>(b2, spars);
    repair1_kernel<<<dim3(NFIX_MAX, 16), 256>>>(X, W1);
    repair2_kernel<<<NFIX_MAX, 256>>>(b1, W2, b2, spars);
    select_kernel<<<B_ROWS, 256>>>(X, sparse_x, mask, actsp);
    l1_reduce_kernel<<<1, 256>>>(l1);
}